// round 12
// baseline (speedup 1.0000x reference)
#include <cuda_runtime.h>
#include <cuda_fp16.h>
#include <cstdint>
#include <math.h>

#define NROW 4096
#define BATCH 2048
#define INV_T 14.285714285714286f
#define K2C   20.609929155556625f   /* INV_T * log2(e) */
#define NCHUNK 4

__device__ __half   g_fh[NROW * 256];          // normalized features, fp16, [i][e]
__device__ unsigned g_bits[BATCH];
__device__ float    g_part[NCHUNK][NROW][12];  // [0..3]=s[h], [4]=A, [5..8]=C[0..3], [9]=den, pad

// ---------------------------------------------------------------------------
__device__ __forceinline__ uint32_t smem_u32(const void* p) {
    uint32_t a;
    asm("{ .reg .u64 t; cvta.to.shared.u64 t, %1; cvt.u32.u64 %0, t; }" : "=r"(a) : "l"(p));
    return a;
}
__device__ __forceinline__ float fexp2(float x) {
    float y; asm("ex2.approx.f32 %0, %1;" : "=f"(y) : "f"(x)); return y;
}

#define CP_ASYNC(dst, src) asm volatile("cp.async.cg.shared.global [%0], [%1], 16;" :: "r"(dst), "l"(src) : "memory")
#define CP_COMMIT()        asm volatile("cp.async.commit_group;" ::: "memory")
#define CP_WAIT0()         asm volatile("cp.async.wait_group 0;" ::: "memory")

#define LDM4(R, addr) asm volatile( \
    "ldmatrix.sync.aligned.m8n8.x4.shared.b16 {%0,%1,%2,%3}, [%4];" \
    : "=r"((R)[0]), "=r"((R)[1]), "=r"((R)[2]), "=r"((R)[3]) : "r"(addr))

#define LDM2(R, addr) asm volatile( \
    "ldmatrix.sync.aligned.m8n8.x2.shared.b16 {%0,%1}, [%2];" \
    : "=r"((R)[0]), "=r"((R)[1]) : "r"(addr))

#define MMA16816(C, A, b0, b1) asm volatile( \
    "mma.sync.aligned.m16n8k16.row.col.f32.f16.f16.f32 " \
    "{%0,%1,%2,%3}, {%4,%5,%6,%7}, {%8,%9}, {%0,%1,%2,%3};" \
    : "+f"((C)[0]), "+f"((C)[1]), "+f"((C)[2]), "+f"((C)[3]) \
    : "r"((A)[0]), "r"((A)[1]), "r"((A)[2]), "r"((A)[3]), "r"(b0), "r"(b1))

// ---------------------------------------------------------------------------
// Normalize per (row, head) + pack label bits. 4 rows/block, float4 I/O.
// (R10-validated: ~5.1 us)
__global__ void k_norm(const float* __restrict__ feats,
                       const float* __restrict__ labels) {
    const int tid = threadIdx.x;
    const int r = tid >> 6, t = tid & 63;
    const int i = blockIdx.x * 4 + r;
    const int v = i >> 11, b = i & (BATCH - 1);

    float4 val = *(const float4*)&feats[b * 512 + v * 256 + 4 * t];
    float sq = val.x * val.x + val.y * val.y + val.z * val.z + val.w * val.w;
    #pragma unroll
    for (int off = 1; off <= 8; off <<= 1)
        sq += __shfl_xor_sync(0xffffffffu, sq, off);   // 16-lane head groups
    float rn = rsqrtf(fmaxf(sq, 1e-24f));

    union { __half2 h[2]; uint2 u; } cvt;
    cvt.h[0] = __floats2half2_rn(val.x * rn, val.y * rn);
    cvt.h[1] = __floats2half2_rn(val.z * rn, val.w * rn);
    *(uint2*)&g_fh[i * 256 + 4 * t] = cvt.u;

    if (i < BATCH && t == 0) {
        unsigned m = 0;
        #pragma unroll
        for (int c = 0; c < 10; ++c)
            if (labels[i * 10 + c] > 0.5f) m |= (1u << c);
        g_bits[i] = m;
    }
}

// ---------------------------------------------------------------------------
// Tile loader: ROWS rows x 4 heads x 64 fp16 (head blocks of ROWS*128B,
// 128B rows, 16B-chunk swizzle chunk' = chunk ^ (row & 7)).
// ---------------------------------------------------------------------------
template<int ROWS>
__device__ __forceinline__ void prefetch_T(uint32_t Tb, const __half* gT, int tid) {
    #pragma unroll
    for (int q = 0; q < ROWS / 8; ++q) {
        int idx = q * 256 + tid;
        int r = idx >> 5, cc = idx & 31;
        int h = cc >> 3, c = cc & 7;
        uint32_t dst = Tb + h * (ROWS * 128) + r * 128 + ((c ^ (r & 7)) << 4);
        const void* src = gT + r * 256 + h * 64 + c * 8;
        CP_ASYNC(dst, src);
    }
}

// ---------------------------------------------------------------------------
// Per-tile epilogue. acc[h][ms][f]; 8 cells/thread. DIAG: tile may hold i==j.
// (R5-validated)
// ---------------------------------------------------------------------------
template<bool DIAG>
__device__ __forceinline__ void epi(
    const float (&acc)[4][2][4], int j0, int wj, int lane,
    const int (&ig)[4], const unsigned (&ibit)[4],
    float (&s)[4][4], float (&Aa)[4], float (&dn)[4],
    unsigned (&Clo)[4], unsigned (&Chi)[4])
{
    const int cbase = j0 + wj * 8 + 2 * (lane & 3);
    const uint2 jb2 = __ldg((const uint2*)&g_bits[cbase & (BATCH - 1)]);
    const unsigned jb[2] = {jb2.x, jb2.y};

    #pragma unroll
    for (int ms = 0; ms < 2; ++ms)
        #pragma unroll
        for (int fh = 0; fh < 2; ++fh) {
            const int ri = ms * 2 + fh;
            #pragma unroll
            for (int cp = 0; cp < 2; ++cp) {
                const int f = fh * 2 + cp;
                const float d0 = acc[0][ms][f];
                const float d1 = acc[1][ms][f];
                const float d2 = acc[2][ms][f];
                const float d3 = acc[3][ms][f];
                const float best = fmaxf(fmaxf(d0, d1), fmaxf(d2, d3));
                const float e0 = fexp2(fmaf(d0, K2C, -K2C));
                const float e1 = fexp2(fmaf(d1, K2C, -K2C));
                const float e2 = fexp2(fmaf(d2, K2C, -K2C));
                const float e3 = fexp2(fmaf(d3, K2C, -K2C));
                bool nd = true;
                if (DIAG) nd = ((cbase + cp) != ig[ri]);
                if (!DIAG || nd) {
                    s[ri][0] += e0; s[ri][1] += e1;
                    s[ri][2] += e2; s[ri][3] += e3;
                }
                bool p = ((ibit[ri] & jb[cp]) != 0u);
                if (DIAG) p = p && nd;
                if (p) {
                    Aa[ri] += best;
                    dn[ri] += 1.0f;
                    if (d0 == best) Clo[ri] += 1u;
                    if (d1 == best) Clo[ri] += 0x10000u;
                    if (d2 == best) Chi[ri] += 1u;
                    if (d3 == best) Chi[ri] += 0x10000u;
                }
            }
        }
}

// ---------------------------------------------------------------------------
// Main: fp16 mma.sync GEMM + fused epilogue (R5-validated layout, best main).
// Grid (4 j-chunks, 64 i-tiles) = 256 CTAs; 256 threads = 8 warps (2i x 4j).
// CTA tile: 64 i x 1024 j x 4 heads, j streamed in 32 tiles of 32.
// occupancy 2, ~96 regs. SMEM: A 32KB | B0 16KB | B1 16KB | red 2.5KB.
// ---------------------------------------------------------------------------
__global__ __launch_bounds__(256, 2) void k_main() {
    extern __shared__ unsigned char smraw[];
    uint32_t raw  = smem_u32(smraw);
    uint32_t base = (raw + 127) & ~127u;
    unsigned char* sm = smraw + (base - raw);

    const uint32_t Ab  = base;
    const uint32_t B0b = base + 32768;
    const uint32_t B1b = base + 49152;
    float* red = (float*)(sm + 65536);     // 64 rows x 10 floats

    const int tid = threadIdx.x;
    const int lane = tid & 31, wid = tid >> 5;
    const int wi = wid >> 2, wj = wid & 3;          // 2 i-warps x 4 j-warps
    const int by = blockIdx.y, jc = blockIdx.x;
    const int i0 = by * 64;
    const int jbase = jc * 1024;
    const bool has_diag = (jc == (by >> 4));
    const int  jt_d0 = (by & 15) * 2;               // diag spans 2 j-tiles of 32

    prefetch_T<64>(Ab, g_fh + (size_t)i0 * 256, tid);
    prefetch_T<32>(B0b, g_fh + (size_t)jbase * 256, tid);
    CP_COMMIT();

    // ldmatrix geometry
    const int l7 = lane & 7;
    const int khA = (lane >> 4) & 1;
    const uint32_t aoff0 = (uint32_t)((wi * 32 + (lane & 8) + l7) * 128);
    const uint32_t aoff1 = aoff0 + 2048;
    const int khB = (lane >> 3) & 1;
    const uint32_t boff = (uint32_t)((wj * 8 + l7) * 128);

    int ig[4]; unsigned ibit[4];
    #pragma unroll
    for (int ri = 0; ri < 4; ++ri) {
        ig[ri] = i0 + wi * 32 + (ri >> 1) * 16 + (ri & 1) * 8 + (lane >> 2);
        ibit[ri] = __ldg(&g_bits[ig[ri] & (BATCH - 1)]);
    }

    float s[4][4], Aa[4], dn[4];
    unsigned Clo[4], Chi[4];
    #pragma unroll
    for (int ri = 0; ri < 4; ++ri) {
        Aa[ri] = 0.f; dn[ri] = 0.f; Clo[ri] = 0u; Chi[ri] = 0u;
        #pragma unroll
        for (int h = 0; h < 4; ++h) s[ri][h] = 0.f;
    }

    for (int jt = 0; jt < 32; ++jt) {
        const uint32_t Bb = (jt & 1) ? B1b : B0b;
        const int j0 = jbase + jt * 32;

        CP_WAIT0();
        __syncthreads();
        if (jt + 1 < 32)
            prefetch_T<32>((jt & 1) ? B0b : B1b, g_fh + (size_t)(j0 + 32) * 256, tid);
        CP_COMMIT();

        float acc[4][2][4];
        #pragma unroll
        for (int h = 0; h < 4; ++h)
            #pragma unroll
            for (int ms = 0; ms < 2; ++ms)
                #pragma unroll
                for (int f = 0; f < 4; ++f) acc[h][ms][f] = 0.f;

        #pragma unroll
        for (int h = 0; h < 4; ++h) {
            const uint32_t Ah = Ab + h * 8192;
            const uint32_t Bh = Bb + h * 4096;
            #pragma unroll
            for (int ks = 0; ks < 4; ++ks) {
                uint32_t A0[4], A1[4], Bq[2];
                uint32_t swA = (uint32_t)(((ks * 2 + khA) ^ l7) << 4);
                uint32_t swB = (uint32_t)(((ks * 2 + khB) ^ l7) << 4);
                LDM4(A0, Ah + aoff0 + swA);
                LDM4(A1, Ah + aoff1 + swA);
                LDM2(Bq, Bh + boff + swB);
                MMA16816(acc[h][0], A0, Bq[0], Bq[1]);
                MMA16816(acc[h][1], A1, Bq[0], Bq[1]);
            }
        }

        if (has_diag && (jt == jt_d0 || jt == jt_d0 + 1))
            epi<true >(acc, j0, wj, lane, ig, ibit, s, Aa, dn, Clo, Chi);
        else
            epi<false>(acc, j0, wj, lane, ig, ibit, s, Aa, dn, Clo, Chi);
    }

    // ---- lane-group reduce (4 lanes share rows) ----
    #pragma unroll
    for (int off = 1; off <= 2; off <<= 1) {
        #pragma unroll
        for (int ri = 0; ri < 4; ++ri) {
            #pragma unroll
            for (int h = 0; h < 4; ++h)
                s[ri][h] += __shfl_xor_sync(0xffffffffu, s[ri][h], off);
            Aa[ri]  += __shfl_xor_sync(0xffffffffu, Aa[ri], off);
            dn[ri]  += __shfl_xor_sync(0xffffffffu, dn[ri], off);
            Clo[ri] += __shfl_xor_sync(0xffffffffu, Clo[ri], off);
            Chi[ri] += __shfl_xor_sync(0xffffffffu, Chi[ri], off);
        }
    }

    // ---- cross-warp combine (4 j-warps), sequential phases ----
    __syncthreads();
    #pragma unroll
    for (int ph = 0; ph < 4; ++ph) {
        if (wj == ph && (lane & 3) == 0) {
            #pragma unroll
            for (int ri = 0; ri < 4; ++ri) {
                int row = wi * 32 + (ri >> 1) * 16 + (ri & 1) * 8 + (lane >> 2);
                float* p = &red[row * 10];
                float c0 = (float)(Clo[ri] & 0xFFFFu), c1 = (float)(Clo[ri] >> 16);
                float c2 = (float)(Chi[ri] & 0xFFFFu), c3 = (float)(Chi[ri] >> 16);
                if (ph == 0) {
                    p[0] = s[ri][0]; p[1] = s[ri][1]; p[2] = s[ri][2]; p[3] = s[ri][3];
                    p[4] = Aa[ri];   p[5] = c0; p[6] = c1; p[7] = c2; p[8] = c3;
                    p[9] = dn[ri];
                } else {
                    p[0] += s[ri][0]; p[1] += s[ri][1]; p[2] += s[ri][2]; p[3] += s[ri][3];
                    p[4] += Aa[ri];   p[5] += c0; p[6] += c1; p[7] += c2; p[8] += c3;
                    p[9] += dn[ri];
                }
            }
        }
        __syncthreads();
    }
    if (tid < 64) {
        const float* p = &red[tid * 10];
        float* o = g_part[jc][i0 + tid];
        #pragma unroll
        for (int q = 0; q < 10; ++q) o[q] = p[q];
    }
}

// ---------------------------------------------------------------------------
// Merged loss + finite-filtered mean. Single CTA, vectorized loads.
__global__ void k_lossfinal(float* __restrict__ out) {
    const int t = threadIdx.x;   // 256
    float lsum = 0.f, lcnt = 0.f;
    #pragma unroll 2
    for (int r = 0; r < 16; ++r) {
        const int i = r * 256 + t;
        float s0 = 0, s1 = 0, s2 = 0, s3 = 0;
        float A = 0, c0 = 0, c1 = 0, c2 = 0, c3 = 0, dnm = 0;
        #pragma unroll
        for (int c = 0; c < NCHUNK; ++c) {
            const float* p = g_part[c][i];
            float4 qa = *(const float4*)p;
            float4 qb = *(const float4*)(p + 4);
            float2 qc = *(const float2*)(p + 8);
            s0 += qa.x; s1 += qa.y; s2 += qa.z; s3 += qa.w;
            A += qb.x; c0 += qb.y; c1 += qb.z; c2 += qb.w;
            c3 += qc.x; dnm += qc.y;
        }
        float sub = c0 * (INV_T + __logf(s0)) + c1 * (INV_T + __logf(s1))
                  + c2 * (INV_T + __logf(s2)) + c3 * (INV_T + __logf(s3));
        float loss = -(A * INV_T - sub) / dnm;
        if (isfinite(loss)) { lsum += loss; lcnt += 1.f; }
    }
    __shared__ float bs[256], bc[256];
    bs[t] = lsum; bc[t] = lcnt;
    __syncthreads();
    for (int st = 128; st > 0; st >>= 1) {
        if (t < st) { bs[t] += bs[t + st]; bc[t] += bc[t + st]; }
        __syncthreads();
    }
    if (t == 0) out[0] = bs[0] / bc[0];
}

// ---------------------------------------------------------------------------
extern "C" void kernel_launch(void* const* d_in, const int* in_sizes, int n_in,
                              void* d_out, int out_size) {
    const float* feats  = (const float*)d_in[0];   // (2048, 2, 256) fp32
    const float* labels = (const float*)d_in[1];   // (2048, 10) fp32
    (void)in_sizes; (void)n_in; (void)out_size;

    k_norm<<<NROW / 4, 256>>>(feats, labels);

    const int shmem = 65536 + 2560 + 128;   // A+B0+B1 | red | slack
    cudaFuncSetAttribute(k_main, cudaFuncAttributeMaxDynamicSharedMemorySize, shmem);
    dim3 grid(NCHUNK, 64);
    k_main<<<grid, 256, shmem>>>();

    k_lossfinal<<<1, 256>>>((float*)d_out);
}

// round 14
// speedup vs baseline: 1.1254x; 1.1254x over previous
#include <cuda_runtime.h>
#include <cuda_fp16.h>
#include <cstdint>
#include <math.h>

#define NROW 4096
#define BATCH 2048
#define INV_T 14.285714285714286f
#define K2C   20.609929155556625f   /* INV_T * log2(e) */
#define NCHUNK 4

__device__ __half   g_fh[NROW * 256];          // normalized features, fp16, [i][e]
__device__ unsigned g_bits[BATCH];
__device__ float    g_part[NCHUNK][NROW][12];  // [0..3]=s[h], [4]=A, [5..8]=C[0..3], [9]=den, pad
__device__ float    g_red[64];
__device__ unsigned g_done = 0;

// ---------------------------------------------------------------------------
__device__ __forceinline__ uint32_t smem_u32(const void* p) {
    uint32_t a;
    asm("{ .reg .u64 t; cvta.to.shared.u64 t, %1; cvt.u32.u64 %0, t; }" : "=r"(a) : "l"(p));
    return a;
}
__device__ __forceinline__ float fexp2(float x) {
    float y; asm("ex2.approx.f32 %0, %1;" : "=f"(y) : "f"(x)); return y;
}

#define CP_ASYNC(dst, src) asm volatile("cp.async.cg.shared.global [%0], [%1], 16;" :: "r"(dst), "l"(src) : "memory")
#define CP_COMMIT()        asm volatile("cp.async.commit_group;" ::: "memory")
#define CP_WAIT0()         asm volatile("cp.async.wait_group 0;" ::: "memory")

#define LDM4(R, addr) asm volatile( \
    "ldmatrix.sync.aligned.m8n8.x4.shared.b16 {%0,%1,%2,%3}, [%4];" \
    : "=r"((R)[0]), "=r"((R)[1]), "=r"((R)[2]), "=r"((R)[3]) : "r"(addr))

#define LDM2(R, addr) asm volatile( \
    "ldmatrix.sync.aligned.m8n8.x2.shared.b16 {%0,%1}, [%2];" \
    : "=r"((R)[0]), "=r"((R)[1]) : "r"(addr))

#define MMA16816(C, A, b0, b1) asm volatile( \
    "mma.sync.aligned.m16n8k16.row.col.f32.f16.f16.f32 " \
    "{%0,%1,%2,%3}, {%4,%5,%6,%7}, {%8,%9}, {%0,%1,%2,%3};" \
    : "+f"((C)[0]), "+f"((C)[1]), "+f"((C)[2]), "+f"((C)[3]) \
    : "r"((A)[0]), "r"((A)[1]), "r"((A)[2]), "r"((A)[3]), "r"(b0), "r"(b1))

// ---------------------------------------------------------------------------
// Normalize per (row, head) + pack label bits. 4 rows/block, float4 I/O.
// (measured ~5.4 us)
__global__ void k_norm(const float* __restrict__ feats,
                       const float* __restrict__ labels) {
    const int tid = threadIdx.x;
    const int r = tid >> 6, t = tid & 63;
    const int i = blockIdx.x * 4 + r;
    const int v = i >> 11, b = i & (BATCH - 1);

    float4 val = *(const float4*)&feats[b * 512 + v * 256 + 4 * t];
    float sq = val.x * val.x + val.y * val.y + val.z * val.z + val.w * val.w;
    #pragma unroll
    for (int off = 1; off <= 8; off <<= 1)
        sq += __shfl_xor_sync(0xffffffffu, sq, off);   // 16-lane head groups
    float rn = rsqrtf(fmaxf(sq, 1e-24f));

    union { __half2 h[2]; uint2 u; } cvt;
    cvt.h[0] = __floats2half2_rn(val.x * rn, val.y * rn);
    cvt.h[1] = __floats2half2_rn(val.z * rn, val.w * rn);
    *(uint2*)&g_fh[i * 256 + 4 * t] = cvt.u;

    if (i < BATCH && t == 0) {
        unsigned m = 0;
        #pragma unroll
        for (int c = 0; c < 10; ++c)
            if (labels[i * 10 + c] > 0.5f) m |= (1u << c);
        g_bits[i] = m;
    }
}

// ---------------------------------------------------------------------------
// Tile loader: ROWS rows x 4 heads x 64 fp16 (head blocks of ROWS*128B,
// 128B rows, 16B-chunk swizzle chunk' = chunk ^ (row & 7)).
// ---------------------------------------------------------------------------
template<int ROWS>
__device__ __forceinline__ void prefetch_T(uint32_t Tb, const __half* gT, int tid) {
    #pragma unroll
    for (int q = 0; q < ROWS / 8; ++q) {
        int idx = q * 256 + tid;
        int r = idx >> 5, cc = idx & 31;
        int h = cc >> 3, c = cc & 7;
        uint32_t dst = Tb + h * (ROWS * 128) + r * 128 + ((c ^ (r & 7)) << 4);
        const void* src = gT + r * 256 + h * 64 + c * 8;
        CP_ASYNC(dst, src);
    }
}

// ---------------------------------------------------------------------------
// Per-tile epilogue. acc[h][ms][f]; 8 cells/thread. DIAG: tile may hold i==j.
// (R5-validated)
// ---------------------------------------------------------------------------
template<bool DIAG>
__device__ __forceinline__ void epi(
    const float (&acc)[4][2][4], int j0, int wj, int lane,
    const int (&ig)[4], const unsigned (&ibit)[4],
    float (&s)[4][4], float (&Aa)[4], float (&dn)[4],
    unsigned (&Clo)[4], unsigned (&Chi)[4])
{
    const int cbase = j0 + wj * 8 + 2 * (lane & 3);
    const uint2 jb2 = __ldg((const uint2*)&g_bits[cbase & (BATCH - 1)]);
    const unsigned jb[2] = {jb2.x, jb2.y};

    #pragma unroll
    for (int ms = 0; ms < 2; ++ms)
        #pragma unroll
        for (int fh = 0; fh < 2; ++fh) {
            const int ri = ms * 2 + fh;
            #pragma unroll
            for (int cp = 0; cp < 2; ++cp) {
                const int f = fh * 2 + cp;
                const float d0 = acc[0][ms][f];
                const float d1 = acc[1][ms][f];
                const float d2 = acc[2][ms][f];
                const float d3 = acc[3][ms][f];
                const float best = fmaxf(fmaxf(d0, d1), fmaxf(d2, d3));
                const float e0 = fexp2(fmaf(d0, K2C, -K2C));
                const float e1 = fexp2(fmaf(d1, K2C, -K2C));
                const float e2 = fexp2(fmaf(d2, K2C, -K2C));
                const float e3 = fexp2(fmaf(d3, K2C, -K2C));
                bool nd = true;
                if (DIAG) nd = ((cbase + cp) != ig[ri]);
                if (!DIAG || nd) {
                    s[ri][0] += e0; s[ri][1] += e1;
                    s[ri][2] += e2; s[ri][3] += e3;
                }
                bool p = ((ibit[ri] & jb[cp]) != 0u);
                if (DIAG) p = p && nd;
                if (p) {
                    Aa[ri] += best;
                    dn[ri] += 1.0f;
                    if (d0 == best) Clo[ri] += 1u;
                    if (d1 == best) Clo[ri] += 0x10000u;
                    if (d2 == best) Chi[ri] += 1u;
                    if (d3 == best) Chi[ri] += 0x10000u;
                }
            }
        }
}

// ---------------------------------------------------------------------------
// Main: fp16 mma.sync GEMM + fused epilogue (R5-validated layout, best main).
// Grid (4 j-chunks, 64 i-tiles) = 256 CTAs; 256 threads = 8 warps (2i x 4j).
// CTA tile: 64 i x 1024 j x 4 heads, j streamed in 32 tiles of 32.
// occupancy 2, ~96 regs. SMEM: A 32KB | B0 16KB | B1 16KB | red 2.5KB.
// ---------------------------------------------------------------------------
__global__ __launch_bounds__(256, 2) void k_main() {
    extern __shared__ unsigned char smraw[];
    uint32_t raw  = smem_u32(smraw);
    uint32_t base = (raw + 127) & ~127u;
    unsigned char* sm = smraw + (base - raw);

    const uint32_t Ab  = base;
    const uint32_t B0b = base + 32768;
    const uint32_t B1b = base + 49152;
    float* red = (float*)(sm + 65536);     // 64 rows x 10 floats

    const int tid = threadIdx.x;
    const int lane = tid & 31, wid = tid >> 5;
    const int wi = wid >> 2, wj = wid & 3;          // 2 i-warps x 4 j-warps
    const int by = blockIdx.y, jc = blockIdx.x;
    const int i0 = by * 64;
    const int jbase = jc * 1024;
    const bool has_diag = (jc == (by >> 4));
    const int  jt_d0 = (by & 15) * 2;               // diag spans 2 j-tiles of 32

    prefetch_T<64>(Ab, g_fh + (size_t)i0 * 256, tid);
    prefetch_T<32>(B0b, g_fh + (size_t)jbase * 256, tid);
    CP_COMMIT();

    // ldmatrix geometry
    const int l7 = lane & 7;
    const int khA = (lane >> 4) & 1;
    const uint32_t aoff0 = (uint32_t)((wi * 32 + (lane & 8) + l7) * 128);
    const uint32_t aoff1 = aoff0 + 2048;
    const int khB = (lane >> 3) & 1;
    const uint32_t boff = (uint32_t)((wj * 8 + l7) * 128);

    int ig[4]; unsigned ibit[4];
    #pragma unroll
    for (int ri = 0; ri < 4; ++ri) {
        ig[ri] = i0 + wi * 32 + (ri >> 1) * 16 + (ri & 1) * 8 + (lane >> 2);
        ibit[ri] = __ldg(&g_bits[ig[ri] & (BATCH - 1)]);
    }

    float s[4][4], Aa[4], dn[4];
    unsigned Clo[4], Chi[4];
    #pragma unroll
    for (int ri = 0; ri < 4; ++ri) {
        Aa[ri] = 0.f; dn[ri] = 0.f; Clo[ri] = 0u; Chi[ri] = 0u;
        #pragma unroll
        for (int h = 0; h < 4; ++h) s[ri][h] = 0.f;
    }

    for (int jt = 0; jt < 32; ++jt) {
        const uint32_t Bb = (jt & 1) ? B1b : B0b;
        const int j0 = jbase + jt * 32;

        CP_WAIT0();
        __syncthreads();
        if (jt + 1 < 32)
            prefetch_T<32>((jt & 1) ? B0b : B1b, g_fh + (size_t)(j0 + 32) * 256, tid);
        CP_COMMIT();

        float acc[4][2][4];
        #pragma unroll
        for (int h = 0; h < 4; ++h)
            #pragma unroll
            for (int ms = 0; ms < 2; ++ms)
                #pragma unroll
                for (int f = 0; f < 4; ++f) acc[h][ms][f] = 0.f;

        #pragma unroll
        for (int h = 0; h < 4; ++h) {
            const uint32_t Ah = Ab + h * 8192;
            const uint32_t Bh = Bb + h * 4096;
            #pragma unroll
            for (int ks = 0; ks < 4; ++ks) {
                uint32_t A0[4], A1[4], Bq[2];
                uint32_t swA = (uint32_t)(((ks * 2 + khA) ^ l7) << 4);
                uint32_t swB = (uint32_t)(((ks * 2 + khB) ^ l7) << 4);
                LDM4(A0, Ah + aoff0 + swA);
                LDM4(A1, Ah + aoff1 + swA);
                LDM2(Bq, Bh + boff + swB);
                MMA16816(acc[h][0], A0, Bq[0], Bq[1]);
                MMA16816(acc[h][1], A1, Bq[0], Bq[1]);
            }
        }

        if (has_diag && (jt == jt_d0 || jt == jt_d0 + 1))
            epi<true >(acc, j0, wj, lane, ig, ibit, s, Aa, dn, Clo, Chi);
        else
            epi<false>(acc, j0, wj, lane, ig, ibit, s, Aa, dn, Clo, Chi);
    }

    // ---- lane-group reduce (4 lanes share rows) ----
    #pragma unroll
    for (int off = 1; off <= 2; off <<= 1) {
        #pragma unroll
        for (int ri = 0; ri < 4; ++ri) {
            #pragma unroll
            for (int h = 0; h < 4; ++h)
                s[ri][h] += __shfl_xor_sync(0xffffffffu, s[ri][h], off);
            Aa[ri]  += __shfl_xor_sync(0xffffffffu, Aa[ri], off);
            dn[ri]  += __shfl_xor_sync(0xffffffffu, dn[ri], off);
            Clo[ri] += __shfl_xor_sync(0xffffffffu, Clo[ri], off);
            Chi[ri] += __shfl_xor_sync(0xffffffffu, Chi[ri], off);
        }
    }

    // ---- cross-warp combine (4 j-warps), sequential phases ----
    __syncthreads();
    #pragma unroll
    for (int ph = 0; ph < 4; ++ph) {
        if (wj == ph && (lane & 3) == 0) {
            #pragma unroll
            for (int ri = 0; ri < 4; ++ri) {
                int row = wi * 32 + (ri >> 1) * 16 + (ri & 1) * 8 + (lane >> 2);
                float* p = &red[row * 10];
                float c0 = (float)(Clo[ri] & 0xFFFFu), c1 = (float)(Clo[ri] >> 16);
                float c2 = (float)(Chi[ri] & 0xFFFFu), c3 = (float)(Chi[ri] >> 16);
                if (ph == 0) {
                    p[0] = s[ri][0]; p[1] = s[ri][1]; p[2] = s[ri][2]; p[3] = s[ri][3];
                    p[4] = Aa[ri];   p[5] = c0; p[6] = c1; p[7] = c2; p[8] = c3;
                    p[9] = dn[ri];
                } else {
                    p[0] += s[ri][0]; p[1] += s[ri][1]; p[2] += s[ri][2]; p[3] += s[ri][3];
                    p[4] += Aa[ri];   p[5] += c0; p[6] += c1; p[7] += c2; p[8] += c3;
                    p[9] += dn[ri];
                }
            }
        }
        __syncthreads();
    }
    if (tid < 64) {
        const float* p = &red[tid * 10];
        float* o = g_part[jc][i0 + tid];
        #pragma unroll
        for (int q = 0; q < 10; ++q) o[q] = p[q];
    }
}

// ---------------------------------------------------------------------------
// Parallel loss (32 CTAs x 128 threads, one row per thread) + fused last-block
// finalize (atomic-counter pattern, validated in R8). Deterministic ordering.
__global__ void k_loss(float* __restrict__ out) {
    const int t = threadIdx.x;
    const int i = blockIdx.x * 128 + t;

    float s0 = 0, s1 = 0, s2 = 0, s3 = 0;
    float A = 0, c0 = 0, c1 = 0, c2 = 0, c3 = 0, dnm = 0;
    #pragma unroll
    for (int c = 0; c < NCHUNK; ++c) {
        const float* p = g_part[c][i];
        float4 qa = *(const float4*)p;
        float4 qb = *(const float4*)(p + 4);
        float2 qc = *(const float2*)(p + 8);
        s0 += qa.x; s1 += qa.y; s2 += qa.z; s3 += qa.w;
        A += qb.x; c0 += qb.y; c1 += qb.z; c2 += qb.w;
        c3 += qc.x; dnm += qc.y;
    }
    float sub = c0 * (INV_T + __logf(s0)) + c1 * (INV_T + __logf(s1))
              + c2 * (INV_T + __logf(s2)) + c3 * (INV_T + __logf(s3));
    float loss = -(A * INV_T - sub) / dnm;
    float ok = isfinite(loss) ? 1.f : 0.f;
    float ls = isfinite(loss) ? loss : 0.f;

    __shared__ float bs[128], bc[128];
    bs[t] = ls; bc[t] = ok;
    __syncthreads();
    for (int st = 64; st > 0; st >>= 1) {
        if (t < st) { bs[t] += bs[t + st]; bc[t] += bc[t + st]; }
        __syncthreads();
    }

    __shared__ unsigned slast;
    if (t == 0) {
        g_red[blockIdx.x * 2]     = bs[0];
        g_red[blockIdx.x * 2 + 1] = bc[0];
        __threadfence();
        unsigned old = atomicAdd(&g_done, 1u);
        slast = (old == 31u) ? 1u : 0u;
    }
    __syncthreads();
    if (slast && t < 32) {
        __threadfence();
        float sv = g_red[2 * t], cv = g_red[2 * t + 1];
        #pragma unroll
        for (int off = 16; off > 0; off >>= 1) {
            sv += __shfl_xor_sync(0xffffffffu, sv, off);
            cv += __shfl_xor_sync(0xffffffffu, cv, off);
        }
        if (t == 0) { out[0] = sv / cv; g_done = 0; }
    }
}

// ---------------------------------------------------------------------------
extern "C" void kernel_launch(void* const* d_in, const int* in_sizes, int n_in,
                              void* d_out, int out_size) {
    const float* feats  = (const float*)d_in[0];   // (2048, 2, 256) fp32
    const float* labels = (const float*)d_in[1];   // (2048, 10) fp32
    (void)in_sizes; (void)n_in; (void)out_size;

    k_norm<<<NROW / 4, 256>>>(feats, labels);

    const int shmem = 65536 + 2560 + 128;   // A+B0+B1 | red | slack
    cudaFuncSetAttribute(k_main, cudaFuncAttributeMaxDynamicSharedMemorySize, shmem);
    dim3 grid(NCHUNK, 64);
    k_main<<<grid, 256, shmem>>>();

    k_loss<<<32, 128>>>((float*)d_out);
}